// round 13
// baseline (speedup 1.0000x reference)
#include <cuda_runtime.h>

#define NX 1024
#define NY 1024
#define NB 8
#define CH (NX*NY)
#define NPTS 8388608.0

// Physics constants
#define PR     0.71f
#define RA_PR  710.0f
#define HA2_PR 71.0f
#define PR_DA  7.1f
#define DIFF_C 1.6666666666666667f
#define QQ     0.1f
#define DTINV  100.0f

__device__ double g_acc = 0.0;   // reset by finalize each call -> replay-safe

// x first+second tgrad for 4 points; E0..E7 = values at x0-2..x0+5. (R5-verified)
__device__ __forceinline__ void xderiv(float4 c, float E0, float E1, float E6, float E7,
                                       int tid, float* dx, float* dxx)
{
    float E2 = c.x, E3 = c.y, E4 = c.z, E5 = c.w;
    if (tid == 0) {
        dx[0]  = E3 - E2;
        dx[1]  = 0.5f * (E4 - E2);
        dxx[0] = 0.5f * E4 - E3 + 0.5f * E2;
        dxx[1] = 0.25f * E5 - 0.75f * E3 + 0.5f * E2;
    } else {
        dx[0]  = 0.5f * (E3 - E1);
        dx[1]  = 0.5f * (E4 - E2);
        dxx[0] = 0.25f * (E4 - 2.0f * E2 + E0);
        dxx[1] = 0.25f * (E5 - 2.0f * E3 + E1);
    }
    if (tid == 255) {
        dx[2]  = 0.5f * (E5 - E3);
        dx[3]  = E5 - E4;
        dxx[2] = 0.5f * E5 - 0.75f * E4 + 0.25f * E2;
        dxx[3] = 0.5f * E5 - E4 + 0.5f * E3;
    } else {
        dx[2]  = 0.5f * (E5 - E3);
        dx[3]  = 0.5f * (E6 - E4);
        dxx[2] = 0.25f * (E6 - 2.0f * E4 + E2);
        dxx[3] = 0.25f * (E7 - 2.0f * E5 + E3);
    }
}

// dx only (for P channel)
__device__ __forceinline__ void xderiv1(float4 c, float E1, float E6,
                                        int tid, float* dx)
{
    float E2 = c.x, E3 = c.y, E4 = c.z, E5 = c.w;
    dx[1] = 0.5f * (E4 - E2);
    dx[2] = 0.5f * (E5 - E3);
    dx[0] = (tid == 0)   ? (E3 - E2) : 0.5f * (E3 - E1);
    dx[3] = (tid == 255) ? (E5 - E4) : 0.5f * (E6 - E4);
}

// x-halo: plain predicated float2 loads at x0-2 and x0+4 (8B-aligned, legal).
// NO shuffles (R9), NO float4 halos (dead lanes W0/W1/W10/W11 removed).
__device__ __forceinline__ void halo2(const float* __restrict__ row, int tid, int x0,
                                      float& E0, float& E1, float& E6, float& E7)
{
    E0 = E1 = E6 = E7 = 0.0f;
    if (tid > 0) {
        float2 l = *(const float2*)(row + x0 - 2);
        E0 = l.x; E1 = l.y;
    }
    if (tid < 255) {
        float2 r = *(const float2*)(row + x0 + 4);
        E6 = r.x; E7 = r.y;
    }
}

struct Deriv { float v[4], dx[4], dy[4], dxx[4], dyy[4]; };

__device__ __forceinline__ void full_derivs(
    const float* __restrict__ ch, int tid, int y, int x0,
    int rM, int rP, float s1,
    int rA, int rB, float cA, float cC, float cB,
    Deriv& d)
{
    const float* rowp = ch + (size_t)y * NX;
    float4 c  = *(const float4*)(rowp + x0);
    float E0, E1, E6, E7;
    halo2(rowp, tid, x0, E0, E1, E6, E7);
    float4 m  = *(const float4*)(ch + (size_t)rM * NX + x0);
    float4 p  = *(const float4*)(ch + (size_t)rP * NX + x0);
    float4 a  = *(const float4*)(ch + (size_t)rA * NX + x0);
    float4 bb = *(const float4*)(ch + (size_t)rB * NX + x0);
    xderiv(c, E0, E1, E6, E7, tid, d.dx, d.dxx);
    const float* C  = (const float*)&c;
    const float* M  = (const float*)&m;  const float* P_ = (const float*)&p;
    const float* A  = (const float*)&a;  const float* B_ = (const float*)&bb;
#pragma unroll
    for (int j = 0; j < 4; j++) {
        d.v[j]   = C[j];
        d.dy[j]  = s1 * (P_[j] - M[j]);
        d.dyy[j] = cA * A[j] + cC * C[j] + cB * B_[j];
    }
}

__global__ __launch_bounds__(256)
void physics_loss_kernel(const float* __restrict__ fno, const float* __restrict__ fne)
{
    const int tid = threadIdx.x;
    const int y   = blockIdx.x;
    const int b   = blockIdx.y;
    const int x0  = tid * 4;

    const int   rM = (y > 0) ? y - 1 : 0;
    const int   rP = (y < NY - 1) ? y + 1 : NY - 1;
    const float s1 = (y == 0 || y == NY - 1) ? 1.0f : 0.5f;

    int rA, rB; float cA, cC, cB;
    if      (y == 0)      { rA = 2;      cA = 0.5f;  cC = 0.5f;   rB = 1;      cB = -1.0f; }
    else if (y == 1)      { rA = 0;      cA = 0.5f;  cC = -0.75f; rB = 3;      cB = 0.25f; }
    else if (y == NY - 2) { rA = NY - 4; cA = 0.25f; cC = -0.75f; rB = NY - 1; cB = 0.5f;  }
    else if (y == NY - 1) { rA = NY - 3; cA = 0.5f;  cC = 0.5f;   rB = NY - 2; cB = -1.0f; }
    else                  { rA = y - 2;  cA = 0.25f; cC = -0.5f;  rB = y + 2;  cB = 0.25f; }

    const size_t base = (size_t)b * 4 * CH;
    const size_t rowo = (size_t)y * NX + x0;

    // f_now fields (U, V, T)
    float4 uo4 = *(const float4*)(fno + base + 0 * (size_t)CH + rowo);
    float4 vo4 = *(const float4*)(fno + base + 1 * (size_t)CH + rowo);
    float4 to4 = *(const float4*)(fno + base + 2 * (size_t)CH + rowo);
    float Uo[4] = {uo4.x, uo4.y, uo4.z, uo4.w};
    float Vo[4] = {vo4.x, vo4.y, vo4.z, vo4.w};
    float To[4] = {to4.x, to4.y, to4.z, to4.w};

    float cont[4], resx[4], resy[4], rest[4];

    Deriv D;
    // ---- U_next ----
    full_derivs(fne + base + 0 * (size_t)CH, tid, y, x0, rM, rP, s1, rA, rB, cA, cC, cB, D);
#pragma unroll
    for (int j = 0; j < 4; j++) {
        float Un = D.v[j];
        cont[j] = D.dx[j];
        resx[j] = (Un - Uo[j]) * DTINV + Un * D.dx[j] + Vo[j] * D.dy[j]
                  - PR * (D.dxx[j] + D.dyy[j]) + PR_DA * Un;
    }
    // ---- V_next ----
    full_derivs(fne + base + 1 * (size_t)CH, tid, y, x0, rM, rP, s1, rA, rB, cA, cC, cB, D);
#pragma unroll
    for (int j = 0; j < 4; j++) {
        float Vn = D.v[j];
        cont[j] += D.dy[j];
        resy[j] = (Vn - Vo[j]) * DTINV + Uo[j] * D.dx[j] + Vn * D.dy[j]
                  - PR * (D.dxx[j] + D.dyy[j]) + (HA2_PR + PR_DA) * Vn;
    }
    // ---- T_next ----
    full_derivs(fne + base + 2 * (size_t)CH, tid, y, x0, rM, rP, s1, rA, rB, cA, cC, cB, D);
#pragma unroll
    for (int j = 0; j < 4; j++) {
        float Tn = D.v[j];
        resy[j] -= RA_PR * Tn;
        rest[j] = (Tn - To[j]) * DTINV + Uo[j] * D.dx[j] + Vo[j] * D.dy[j]
                  - DIFF_C * (D.dxx[j] + D.dyy[j]) - QQ * Tn;
    }
    // ---- P_next (dx, dy only) ----
    {
        const float* Pc = fne + base + 3 * (size_t)CH;
        const float* rowp = Pc + (size_t)y * NX;
        float4 c = *(const float4*)(rowp + x0);
        float E0, E1, E6, E7;
        halo2(rowp, tid, x0, E0, E1, E6, E7);
        float4 m = *(const float4*)(Pc + (size_t)rM * NX + x0);
        float4 p = *(const float4*)(Pc + (size_t)rP * NX + x0);
        float pdx[4];
        xderiv1(c, E1, E6, tid, pdx);
        const float* M = (const float*)&m; const float* P_ = (const float*)&p;
#pragma unroll
        for (int j = 0; j < 4; j++) {
            resx[j] += pdx[j];
            resy[j] += s1 * (P_[j] - M[j]);
        }
    }

    float acc = 0.0f;
#pragma unroll
    for (int j = 0; j < 4; j++) {
        acc += cont[j] * cont[j] + resx[j] * resx[j]
             + resy[j] * resy[j] + rest[j] * rest[j];
    }

    // warp + block reduction, then ONE atomicAdd per CTA (R1-proven cheap tail).
#pragma unroll
    for (int o = 16; o > 0; o >>= 1) acc += __shfl_xor_sync(0xFFFFFFFFu, acc, o);

    __shared__ float ws[8];
    if ((tid & 31) == 0) ws[tid >> 5] = acc;
    __syncthreads();
    if (tid == 0) {
        double s = 0.0;
#pragma unroll
        for (int k = 0; k < 8; k++) s += (double)ws[k];
        atomicAdd(&g_acc, s);
    }
}

__global__ void finalize_kernel(float* __restrict__ out)
{
    double t = g_acc * 1e-4 / NPTS;
    if (t < 1e-10) t = 1e-10;
    if (t > 1.0)   t = 1.0;
    out[0] = (float)t;
    g_acc = 0.0;   // reset for next graph replay (stream-ordered before next main)
}

extern "C" void kernel_launch(void* const* d_in, const int* in_sizes, int n_in,
                              void* d_out, int out_size)
{
    const float* f_now  = (const float*)d_in[0];
    const float* f_next = (const float*)d_in[1];

    dim3 grid(NY, NB);
    physics_loss_kernel<<<grid, 256>>>(f_now, f_next);
    finalize_kernel<<<1, 1>>>((float*)d_out);
}